// round 1
// baseline (speedup 1.0000x reference)
#include <cuda_runtime.h>
#include <cuda_bf16.h>

// Problem constants (fixed by the reference)
#define BB 16
#define LL 2048
#define DD 1024
#define SS 32
#define NUM_BUCKETS 64
#define WIDTH_BUCKET 16
#define LEN_BUCKET 32
#define NUM_LABELS 3

// Scratch: per-example sequence lengths (no cudaMalloc allowed)
__device__ int g_len[BB];

// ---------------------------------------------------------------------------
// Kernel 0: lengths[b] = sum_l attention_mask[b, l]
// ---------------------------------------------------------------------------
__global__ void k_lengths(const int* __restrict__ mask) {
    __shared__ int swarp[8];
    const int b = blockIdx.x;
    const int t = threadIdx.x;  // 256 threads
    int sum = 0;
    const int* row = mask + (size_t)b * LL;
    #pragma unroll
    for (int i = t; i < LL; i += 256) sum += row[i];
    #pragma unroll
    for (int o = 16; o; o >>= 1) sum += __shfl_down_sync(0xffffffffu, sum, o);
    if ((t & 31) == 0) swarp[t >> 5] = sum;
    __syncthreads();
    if (t == 0) {
        int s = 0;
        #pragma unroll
        for (int w = 0; w < 8; ++w) s += swarp[w];
        g_len[b] = s;
    }
}

// ---------------------------------------------------------------------------
// Kernel 1: one block per (b, s). Stream rows [head+1, tail) of encoder_layer,
// compute span mean, fold directly into 3 logits, add bucket embeddings + bias.
// ---------------------------------------------------------------------------
__global__ void __launch_bounds__(256, 8)
k_span(const float* __restrict__ enc,
       const int*   __restrict__ heads,
       const int*   __restrict__ tails,
       const float* __restrict__ wemb,
       const float* __restrict__ lemb,
       const float* __restrict__ clsw,   // [DD+16, 3] row-major
       const float* __restrict__ clsb,   // [3]
       float*       __restrict__ logits) // [BB*SS*3], points into d_out
{
    const int s = blockIdx.x;
    const int b = blockIdx.y;
    const int t = threadIdx.x;  // 256 threads; thread t owns float4 lane t

    const int head  = heads[b * SS + s];
    const int tail  = tails[b * SS + s];
    const int start = head + 1;
    const int cnt   = tail - start;
    const float fcnt = fmaxf((float)(cnt > 0 ? cnt : 0), 1.0f);

    const float4* base = (const float4*)(enc + (size_t)b * LL * DD);
    float4 acc = make_float4(0.f, 0.f, 0.f, 0.f);

    #pragma unroll 4
    for (int p = start; p < tail; ++p) {
        float4 v = base[(size_t)p * (DD / 4) + t];
        acc.x += v.x; acc.y += v.y; acc.z += v.z; acc.w += v.w;
    }
    const float inv = 1.0f / fcnt;
    acc.x *= inv; acc.y *= inv; acc.z *= inv; acc.w *= inv;

    // Partial logits from this thread's 4 dims. cls_w reads are contiguous
    // across threads (floats 12t .. 12t+11) -> coalesced, L2-resident.
    const int d = t * 4;
    float p0, p1, p2;
    {
        const float* w = clsw + (size_t)d * 3;
        p0 = acc.x * w[0]  + acc.y * w[3]  + acc.z * w[6]  + acc.w * w[9];
        p1 = acc.x * w[1]  + acc.y * w[4]  + acc.z * w[7]  + acc.w * w[10];
        p2 = acc.x * w[2]  + acc.y * w[5]  + acc.z * w[8]  + acc.w * w[11];
    }

    // Block reduction of 3 floats across 256 threads.
    #pragma unroll
    for (int o = 16; o; o >>= 1) {
        p0 += __shfl_down_sync(0xffffffffu, p0, o);
        p1 += __shfl_down_sync(0xffffffffu, p1, o);
        p2 += __shfl_down_sync(0xffffffffu, p2, o);
    }
    __shared__ float sred[8][3];
    if ((t & 31) == 0) {
        sred[t >> 5][0] = p0; sred[t >> 5][1] = p1; sred[t >> 5][2] = p2;
    }
    __syncthreads();
    if (t == 0) {
        float l0 = 0.f, l1 = 0.f, l2 = 0.f;
        #pragma unroll
        for (int w = 0; w < 8; ++w) { l0 += sred[w][0]; l1 += sred[w][1]; l2 += sred[w][2]; }

        // width / length bucket embedding contributions (dims DD..DD+15)
        int wb = (tail - head) / WIDTH_BUCKET;
        wb = min(max(wb, 0), NUM_BUCKETS - 1);
        int lb = g_len[b] / LEN_BUCKET;
        lb = min(max(lb, 0), NUM_BUCKETS - 1);

        float e0 = clsb[0], e1 = clsb[1], e2 = clsb[2];
        #pragma unroll
        for (int j = 0; j < 8; ++j) {
            const float wv = wemb[wb * 8 + j];
            const float lv = lemb[lb * 8 + j];
            const float* cw = clsw + (size_t)(DD + j) * 3;
            const float* cl = clsw + (size_t)(DD + 8 + j) * 3;
            e0 += wv * cw[0] + lv * cl[0];
            e1 += wv * cw[1] + lv * cl[1];
            e2 += wv * cw[2] + lv * cl[2];
        }
        float* out = logits + ((size_t)b * SS + s) * 3;
        out[0] = l0 + e0;
        out[1] = l1 + e1;
        out[2] = l2 + e2;
    }
}

// ---------------------------------------------------------------------------
// Kernel 2: cross-entropy with ignore_index=-1 over [BB*SS, 3] logits.
// One block of 512 threads (= number of rows).
// ---------------------------------------------------------------------------
__global__ void k_ce(const float* __restrict__ logits,
                     const int*   __restrict__ labels,
                     float*       __restrict__ loss_out)
{
    const int i = threadIdx.x;  // 0..511, one row each
    float nll = 0.f;
    int valid = 0;
    {
        const float a = logits[i * 3 + 0];
        const float b = logits[i * 3 + 1];
        const float c = logits[i * 3 + 2];
        const float m = fmaxf(a, fmaxf(b, c));
        const float lse = m + logf(expf(a - m) + expf(b - m) + expf(c - m));
        const int lab = labels[i];
        if (lab > -1) {
            valid = 1;
            const int cl = max(lab, 0);
            const float x = (cl == 0) ? a : ((cl == 1) ? b : c);
            nll = lse - x;
        }
    }
    // reduce over 512 threads (16 warps)
    #pragma unroll
    for (int o = 16; o; o >>= 1) {
        nll   += __shfl_down_sync(0xffffffffu, nll, o);
        valid += __shfl_down_sync(0xffffffffu, valid, o);
    }
    __shared__ float snll[16];
    __shared__ int   svld[16];
    if ((i & 31) == 0) { snll[i >> 5] = nll; svld[i >> 5] = valid; }
    __syncthreads();
    if (i == 0) {
        float tn = 0.f; int tv = 0;
        #pragma unroll
        for (int w = 0; w < 16; ++w) { tn += snll[w]; tv += svld[w]; }
        *loss_out = tn / (float)max(tv, 1);
    }
}

// ---------------------------------------------------------------------------
// Launch
// ---------------------------------------------------------------------------
extern "C" void kernel_launch(void* const* d_in, const int* in_sizes, int n_in,
                              void* d_out, int out_size)
{
    const float* enc   = (const float*)d_in[0];  // [16,2048,1024] f32
    const int*   mask  = (const int*)  d_in[1];  // [16,2048] i32
    const int*   heads = (const int*)  d_in[2];  // [16,32] i32
    const int*   tails = (const int*)  d_in[3];  // [16,32] i32
    const int*   labs  = (const int*)  d_in[4];  // [16,32] i32
    const float* wemb  = (const float*)d_in[5];  // [64,8] f32
    const float* lemb  = (const float*)d_in[6];  // [64,8] f32
    const float* clsw  = (const float*)d_in[7];  // [1040,3] f32
    const float* clsb  = (const float*)d_in[8];  // [3] f32

    float* out = (float*)d_out;                  // logits [16*32*3] then loss [1]

    k_lengths<<<BB, 256>>>(mask);
    dim3 grid(SS, BB);
    k_span<<<grid, 256>>>(enc, heads, tails, wemb, lemb, clsw, clsb, out);
    k_ce<<<1, 512>>>(out, labs, out + (size_t)BB * SS * NUM_LABELS);
}

// round 2
// speedup vs baseline: 1.2707x; 1.2707x over previous
#include <cuda_runtime.h>
#include <cuda_bf16.h>

// Problem constants (fixed by the reference)
#define BB 16
#define LL 2048
#define DD 1024
#define SS 32
#define NUM_BUCKETS 64
#define WIDTH_BUCKET 16
#define LEN_BUCKET 32
#define NUM_LABELS 3
#define ROWF (DD / 4)   // float4 per row = 256

// last-block-done counter; reset to 0 by the last block each run (graph-replay safe)
__device__ unsigned g_done = 0;

__global__ void __launch_bounds__(256, 4)
k_fused(const float* __restrict__ enc,
        const int*   __restrict__ mask,
        const int*   __restrict__ heads,
        const int*   __restrict__ tails,
        const int*   __restrict__ labels,
        const float* __restrict__ wemb,
        const float* __restrict__ lemb,
        const float* __restrict__ clsw,   // [DD+16, 3]
        const float* __restrict__ clsb,   // [3]
        float*       __restrict__ out)    // logits [512*3] then loss [1]
{
    const int blk = blockIdx.x;          // 0..511
    const int s = blk & (SS - 1);
    const int b = blk >> 5;
    const int t = threadIdx.x;           // 256 threads; thread t owns float4 lane t

    // ---- per-example length (each block recomputes; mask row is L2-resident) ----
    int msum = 0;
    {
        const int* mrow = mask + (size_t)b * LL;
        #pragma unroll
        for (int i = 0; i < LL / 256; ++i) msum += mrow[t + i * 256];
    }

    // ---- span mean streaming ----
    const int head  = heads[blk];
    const int tail  = tails[blk];
    const int start = head + 1;
    const int cnt   = tail - start;

    const float4* p = (const float4*)enc + (size_t)b * LL * ROWF
                      + (size_t)start * ROWF + t;
    float4 acc = make_float4(0.f, 0.f, 0.f, 0.f);

    if (cnt == 63) {
        // compile-time trip count: deep unroll -> MLP ~7 outstanding LDG.128
        #pragma unroll 7
        for (int i = 0; i < 63; ++i) {
            float4 v = __ldcs(p + (size_t)i * ROWF);   // streaming: read-once data
            acc.x += v.x; acc.y += v.y; acc.z += v.z; acc.w += v.w;
        }
    } else {
        #pragma unroll 4
        for (int i = 0; i < cnt; ++i) {
            float4 v = __ldcs(p + (size_t)i * ROWF);
            acc.x += v.x; acc.y += v.y; acc.z += v.z; acc.w += v.w;
        }
    }
    const float fcnt = fmaxf((float)(cnt > 0 ? cnt : 0), 1.0f);
    const float inv = 1.0f / fcnt;
    acc.x *= inv; acc.y *= inv; acc.z *= inv; acc.w *= inv;

    // ---- fold this thread's 4 dims into 3 partial logits ----
    float p0, p1, p2;
    {
        const float* w = clsw + (size_t)(t * 4) * 3;  // coalesced across threads
        p0 = acc.x * w[0] + acc.y * w[3] + acc.z * w[6] + acc.w * w[9];
        p1 = acc.x * w[1] + acc.y * w[4] + acc.z * w[7] + acc.w * w[10];
        p2 = acc.x * w[2] + acc.y * w[5] + acc.z * w[8] + acc.w * w[11];
    }

    // ---- block reduction of (p0, p1, p2, msum) ----
    #pragma unroll
    for (int o = 16; o; o >>= 1) {
        p0   += __shfl_down_sync(0xffffffffu, p0, o);
        p1   += __shfl_down_sync(0xffffffffu, p1, o);
        p2   += __shfl_down_sync(0xffffffffu, p2, o);
        msum += __shfl_down_sync(0xffffffffu, msum, o);
    }
    __shared__ float sred[8][3];
    __shared__ int   smsk[8];
    if ((t & 31) == 0) {
        sred[t >> 5][0] = p0; sred[t >> 5][1] = p1; sred[t >> 5][2] = p2;
        smsk[t >> 5] = msum;
    }
    __syncthreads();
    if (t == 0) {
        float l0 = 0.f, l1 = 0.f, l2 = 0.f; int len = 0;
        #pragma unroll
        for (int w = 0; w < 8; ++w) {
            l0 += sred[w][0]; l1 += sred[w][1]; l2 += sred[w][2]; len += smsk[w];
        }
        int wb = (tail - head) / WIDTH_BUCKET;
        wb = min(max(wb, 0), NUM_BUCKETS - 1);
        int lb = len / LEN_BUCKET;
        lb = min(max(lb, 0), NUM_BUCKETS - 1);

        float e0 = clsb[0], e1 = clsb[1], e2 = clsb[2];
        #pragma unroll
        for (int j = 0; j < 8; ++j) {
            const float wv = wemb[wb * 8 + j];
            const float lv = lemb[lb * 8 + j];
            const float* cw = clsw + (size_t)(DD + j) * 3;
            const float* cl = clsw + (size_t)(DD + 8 + j) * 3;
            e0 += wv * cw[0] + lv * cl[0];
            e1 += wv * cw[1] + lv * cl[1];
            e2 += wv * cw[2] + lv * cl[2];
        }
        float* o = out + (size_t)blk * 3;
        o[0] = l0 + e0; o[1] = l1 + e1; o[2] = l2 + e2;
    }

    // ---- last-block-done: compute CE in-kernel ----
    __threadfence();
    __shared__ int s_last;
    if (t == 0) s_last = (atomicAdd(&g_done, 1u) == (unsigned)(gridDim.x - 1));
    __syncthreads();
    if (!s_last) return;
    if (t == 0) g_done = 0;   // reset for next graph replay
    __threadfence();          // acquire: all blocks' logits visible

    float nll = 0.f;
    int valid = 0;
    #pragma unroll
    for (int r = t; r < BB * SS; r += 256) {
        const float a = out[r * 3 + 0];
        const float b2 = out[r * 3 + 1];
        const float c = out[r * 3 + 2];
        const float m = fmaxf(a, fmaxf(b2, c));
        const float lse = m + logf(expf(a - m) + expf(b2 - m) + expf(c - m));
        const int lab = labels[r];
        if (lab > -1) {
            valid += 1;
            const int cl = max(lab, 0);
            const float x = (cl == 0) ? a : ((cl == 1) ? b2 : c);
            nll += lse - x;
        }
    }
    #pragma unroll
    for (int o = 16; o; o >>= 1) {
        nll   += __shfl_down_sync(0xffffffffu, nll, o);
        valid += __shfl_down_sync(0xffffffffu, valid, o);
    }
    __shared__ float snll[8];
    __shared__ int   svld[8];
    if ((t & 31) == 0) { snll[t >> 5] = nll; svld[t >> 5] = valid; }
    __syncthreads();
    if (t == 0) {
        float tn = 0.f; int tv = 0;
        #pragma unroll
        for (int w = 0; w < 8; ++w) { tn += snll[w]; tv += svld[w]; }
        out[BB * SS * NUM_LABELS] = tn / (float)max(tv, 1);
    }
}

extern "C" void kernel_launch(void* const* d_in, const int* in_sizes, int n_in,
                              void* d_out, int out_size)
{
    const float* enc   = (const float*)d_in[0];  // [16,2048,1024] f32
    const int*   mask  = (const int*)  d_in[1];  // [16,2048] i32
    const int*   heads = (const int*)  d_in[2];  // [16,32] i32
    const int*   tails = (const int*)  d_in[3];  // [16,32] i32
    const int*   labs  = (const int*)  d_in[4];  // [16,32] i32
    const float* wemb  = (const float*)d_in[5];  // [64,8] f32
    const float* lemb  = (const float*)d_in[6];  // [64,8] f32
    const float* clsw  = (const float*)d_in[7];  // [1040,3] f32
    const float* clsb  = (const float*)d_in[8];  // [3] f32

    k_fused<<<BB * SS, 256>>>(enc, mask, heads, tails, labs,
                              wemb, lemb, clsw, clsb, (float*)d_out);
}